// round 16
// baseline (speedup 1.0000x reference)
#include <cuda_runtime.h>
#include <cstdint>

// Problem constants
#define NB   32
#define LQ   2048
#define LK   2048
#define DIN  32
#define DKQ  20
#define EPS  1e-5f
// fold 1/sqrt(20) * log2(e) into q so scores are in log2 domain
#define QSCALE 0.32258572299984063f   // log2(e)/sqrt(20)
#define BIAS_MASKED (-60000.0f)       // f16-finite; ex2 -> exactly 0

// f16 storage strides (in u32 words = f16 pairs)
#define KWS 12  // K row (global AND smem): feats 0..19 (w0-9), bias@w10, zero w11 -> 48B
#define VWG 16  // V row global: dims 0..31 compact -> 64B
#define VW  20  // V row smem: 16 data words + ones@w16 + zero w17-19 -> 80B
#define QW  16  // Q row: feats 0..19, 1.0@20, zero-pad to 32 f16 -> 64B

typedef unsigned int u32;

// Scratch (allocation-free rule: __device__ globals), f16 pairs as u32
__device__ u32 d_kb[(size_t)NB * LK * KWS];
__device__ u32 d_vb[(size_t)NB * LK * VWG];
__device__ u32 d_qb[(size_t)NB * LQ * QW];

// pack two f32 -> f16x2 (lo = first arg)
__device__ __forceinline__ u32 pack_f16(float lo, float hi) {
    u32 d; asm("cvt.rn.f16x2.f32 %0, %1, %2;" : "=r"(d) : "f"(hi), "f"(lo));
    return d;
}
// dual exp2 on packed f16x2
__device__ __forceinline__ u32 ex2h2(u32 a) {
    u32 d; asm("ex2.approx.f16x2 %0, %1;" : "=r"(d) : "r"(a));
    return d;
}
// m16n8k16 f16 mma: D = A*B + C (fp32 accum)
__device__ __forceinline__ void mma_f16(
    float& d0, float& d1, float& d2, float& d3,
    u32 a0, u32 a1, u32 a2, u32 a3, u32 b0, u32 b1,
    float c0, float c1, float c2, float c3)
{
    asm("mma.sync.aligned.m16n8k16.row.col.f32.f16.f16.f32 "
        "{%0,%1,%2,%3},{%4,%5,%6,%7},{%8,%9},{%10,%11,%12,%13};"
        : "=f"(d0), "=f"(d1), "=f"(d2), "=f"(d3)
        : "r"(a0), "r"(a1), "r"(a2), "r"(a3), "r"(b0), "r"(b1),
          "f"(c0), "f"(c1), "f"(c2), "f"(c3));
}
// m16n8k8 f16 mma (half-depth): covers feats 16..19 + bias + zero pad
__device__ __forceinline__ void mma_f16_k8(
    float& d0, float& d1, float& d2, float& d3,
    u32 a0, u32 a1, u32 b0,
    float c0, float c1, float c2, float c3)
{
    asm("mma.sync.aligned.m16n8k8.row.col.f32.f16.f16.f32 "
        "{%0,%1,%2,%3},{%4,%5},{%6},{%7,%8,%9,%10};"
        : "=f"(d0), "=f"(d1), "=f"(d2), "=f"(d3)
        : "r"(a0), "r"(a1), "r"(b0),
          "f"(c0), "f"(c1), "f"(c2), "f"(c3));
}
__device__ __forceinline__ void cp16(u32 dst, const void* src) {
    asm volatile("cp.async.cg.shared.global [%0], [%1], 16;" :: "r"(dst), "l"(src));
}
#define CP_COMMIT() asm volatile("cp.async.commit_group;")
#define CP_WAIT0()  asm volatile("cp.async.wait_group 0;")

__device__ __forceinline__ float dot4(float4 a, float4 b, float acc) {
    acc = fmaf(a.x, b.x, acc);
    acc = fmaf(a.y, b.y, acc);
    acc = fmaf(a.z, b.z, acc);
    acc = fmaf(a.w, b.w, acc);
    return acc;
}

// ---------------------------------------------------------------------------
// Kernel 1: projections -> f16 (compact layouts), split by blockIdx.y.
// ---------------------------------------------------------------------------
__global__ __launch_bounds__(256) void proj_kernel(
    const float* __restrict__ vals, const float* __restrict__ keys,
    const float* __restrict__ ques, const void* __restrict__ mask_raw,
    const float* __restrict__ Wv, const float* __restrict__ Wk, const float* __restrict__ Wq,
    const float* __restrict__ gk, const float* __restrict__ bk,
    const float* __restrict__ gq, const float* __restrict__ bq)
{
    __shared__ float sW[DIN * DIN];
    __shared__ float sg[DKQ], sb[DKQ];
    __shared__ int s_is_byte;

    int tid  = threadIdx.x;
    int task = blockIdx.y;
    size_t r = (size_t)blockIdx.x * 256 + tid;

    if (task == 0) {
        for (int i = tid; i < DIN * DIN; i += 256) sW[i] = Wv[i];
        __syncthreads();

        float4 xa[8];
        const float4* p4 = (const float4*)(vals + r * DIN);
        #pragma unroll
        for (int i = 0; i < 8; i++) xa[i] = p4[i];

        uint4* o4 = (uint4*)(d_vb + r * VWG);
        #pragma unroll
        for (int half = 0; half < 2; half++) {
            float outr[16];
            #pragma unroll
            for (int o = 0; o < 16; o++) {
                const float4* wr = (const float4*)(sW + (half * 16 + o) * DIN);
                float acc = 0.f;
                #pragma unroll
                for (int d = 0; d < 8; d++) acc = dot4(xa[d], wr[d], acc);
                outr[o] = acc;
            }
            u32 wv[8];
            #pragma unroll
            for (int p = 0; p < 8; p++) wv[p] = pack_f16(outr[2*p], outr[2*p+1]);
            o4[half * 2]     = make_uint4(wv[0], wv[1], wv[2], wv[3]);
            o4[half * 2 + 1] = make_uint4(wv[4], wv[5], wv[6], wv[7]);
        }
    } else {
        const float* W  = (task == 1) ? Wk : Wq;
        const float* gg = (task == 1) ? gk : gq;
        const float* bb = (task == 1) ? bk : bq;
        const float* in = (task == 1) ? keys : ques;
        for (int i = tid; i < DKQ * DIN; i += 256) sW[i] = W[i];
        if (tid < DKQ) { sg[tid] = gg[tid]; sb[tid] = bb[tid]; }
        if (task == 1 && tid == 0) {
            // Detect mask storage: numpy bool (1 byte) vs int32 coercion.
            const unsigned int* wd = (const unsigned int*)mask_raw;
            unsigned int acc = 0;
            for (int k = 0; k < 64; k++) acc |= wd[k] & 0xFFFFFF00u;
            s_is_byte = (acc != 0u);
        }
        __syncthreads();

        float4 xa[8];
        const float4* p4 = (const float4*)(in + r * DIN);
        #pragma unroll
        for (int i = 0; i < 8; i++) xa[i] = p4[i];

        float y[DKQ];
        #pragma unroll
        for (int o = 0; o < DKQ; o++) {
            const float4* wr = (const float4*)(sW + o * DIN);
            float acc = 0.f;
            #pragma unroll
            for (int d = 0; d < 8; d++) acc = dot4(xa[d], wr[d], acc);
            y[o] = acc;
        }
        float m = 0.f;
        #pragma unroll
        for (int c = 0; c < DKQ; c++) m += y[c];
        m *= (1.f / DKQ);
        float v = 0.f;
        #pragma unroll
        for (int c = 0; c < DKQ; c++) { float d = y[c] - m; v += d * d; }
        v *= (1.f / DKQ);
        float rs = rsqrtf(v + EPS);

        if (task == 1) {
            #pragma unroll
            for (int c = 0; c < DKQ; c++) y[c] = (y[c] - m) * rs * sg[c] + sb[c];
            int mv = s_is_byte ? (int)((const unsigned char*)mask_raw)[r]
                               : ((const int*)mask_raw)[r];
            float bias = mv ? BIAS_MASKED : 0.f;   // True masks OUT
            u32 wv[KWS];
            #pragma unroll
            for (int p = 0; p < 10; p++) wv[p] = pack_f16(y[2*p], y[2*p+1]);
            wv[10] = pack_f16(bias, 0.f);
            wv[11] = 0u;
            uint4* o4 = (uint4*)(d_kb + r * KWS);
            #pragma unroll
            for (int i = 0; i < 3; i++)
                o4[i] = make_uint4(wv[4*i], wv[4*i+1], wv[4*i+2], wv[4*i+3]);
        } else {
            #pragma unroll
            for (int c = 0; c < DKQ; c++)
                y[c] = ((y[c] - m) * rs * sg[c] + sb[c]) * QSCALE;
            u32 wv[QW];
            #pragma unroll
            for (int p = 0; p < 10; p++) wv[p] = pack_f16(y[2*p], y[2*p+1]);
            wv[10] = pack_f16(1.0f, 0.f);
            #pragma unroll
            for (int p = 11; p < QW; p++) wv[p] = 0u;
            uint4* o4 = (uint4*)(d_qb + r * QW);
            #pragma unroll
            for (int i = 0; i < 4; i++)
                o4[i] = make_uint4(wv[4*i], wv[4*i+1], wv[4*i+2], wv[4*i+3]);
        }
    }
}

// ---------------------------------------------------------------------------
// Kernel 2: flash attention. 64-thread CTA = 2 warps; each warp handles
// TWO m16 tiles (32 queries) sharing K/V fragments -> CTA covers 64 queries,
// grid stays (LQ/64, NB) = 1024 CTAs (single wave). QK = k16+k8 MMA,
// K frags via 2 ldmatrix, V via ldmatrix, cp.async double-buffered TS=64.
// ---------------------------------------------------------------------------
#define TS 64
#define NT (LK / TS)
#define KT4 (TS * KWS / 4)   // 192 uint4 per K tile
#define VT4 (TS * VWG / 4)   // 256 uint4 per V tile
#define CTN 64               // threads per CTA

__global__ __launch_bounds__(CTN) void attn_kernel(
    const float* __restrict__ ques,
    const float* __restrict__ go, const float* __restrict__ bo,
    float* __restrict__ out)
{
    __shared__ u32 sK[2][TS * KWS];   // 2 x 3072 B
    __shared__ u32 sV[2][TS * VW];    // 2 x 5120 B

    int tid  = threadIdx.x;
    int w    = tid >> 5;
    int lane = tid & 31;
    int g    = lane >> 2;   // group id (0..7)
    int i    = lane & 3;    // thread in group (0..3)
    int b    = blockIdx.y;
    int qbase = blockIdx.x * 64 + w * 32;

    // ---- Q fragments: two m16 tiles x (k16 chunk + k8 chunk) ----
    u32 aq0[2][4], aq1[2][2];
    #pragma unroll
    for (int t = 0; t < 2; t++) {
        const u32* q0p = d_qb + ((size_t)b * LQ + qbase + t * 16 + g) * QW;
        const u32* q1p = q0p + 8 * QW;
        aq0[t][0] = q0p[i];
        aq0[t][1] = q1p[i];
        aq0[t][2] = q0p[i + 4];
        aq0[t][3] = q1p[i + 4];
        aq1[t][0] = q0p[8 + i];
        aq1[t][1] = q1p[8 + i];
    }

    // o[t][nt] nt=0..3: output dims; nt=4: ones-column (denominator)
    float o[2][5][4];
    #pragma unroll
    for (int t = 0; t < 2; t++)
        #pragma unroll
        for (int nt = 0; nt < 5; nt++)
            #pragma unroll
            for (int r = 0; r < 4; r++) o[t][nt][r] = 0.f;

    const u32* kgl = d_kb + (size_t)b * LK * KWS;
    const u32* vgl = d_vb + (size_t)b * LK * VWG;

    u32 sK_u[2], sV_u[2];
    sK_u[0] = (u32)__cvta_generic_to_shared(&sK[0][0]);
    sK_u[1] = (u32)__cvta_generic_to_shared(&sK[1][0]);
    sV_u[0] = (u32)__cvta_generic_to_shared(&sV[0][0]);
    sV_u[1] = (u32)__cvta_generic_to_shared(&sV[1][0]);

    // ---- one-time: ones-column + pad words (w16..w19) for BOTH V buffers ----
    #pragma unroll
    for (int it = 0; it < 2; it++) {
        int idx = tid + it * CTN;       // 0..127 over 2 bufs x 64 rows
        int buf = idx >> 6, row = idx & 63;
        uint4* p = (uint4*)(&sV[buf][row * VW + 16]);
        *p = make_uint4(pack_f16(1.0f, 0.f), 0u, 0u, 0u);
    }

    // ---- preamble: async load tile 0 ----
    {
        #pragma unroll
        for (int rr = 0; rr < 3; rr++) {
            int idx = tid + rr * CTN;
            if (idx < KT4) cp16(sK_u[0] + idx * 16, kgl + idx * 4);
        }
        #pragma unroll
        for (int rr = 0; rr < 4; rr++) {
            int idx = tid + rr * CTN;
            int row = idx >> 2, mm = idx & 3;
            cp16(sV_u[0] + (row * VW + mm * 4) * 4, vgl + idx * 4);
        }
        CP_COMMIT();
    }

    // per-lane constant parts of the ldmatrix-K addresses
    int kmM  = lane >> 3;          // matrix id 0..3 (x4)
    int kmR  = lane & 7;           // row within matrix
    int kOff4 = ((kmM >> 1) * 8 + kmR) * KWS + (kmM & 1) * 4;  // words
    int kOff2 = (((lane >> 3) & 1) * 8 + kmR) * KWS + 8;       // words

    for (int t0 = 0; t0 < NT; t0++) {
        int cur = t0 & 1;
        CP_WAIT0();
        __syncthreads();   // tile t0 ready; all warps done with buffer we refill

        // prefetch tile t0+1 (overlaps with compute below)
        if (t0 + 1 < NT) {
            int nxt = cur ^ 1;
            const u32* kg2 = kgl + (size_t)(t0 + 1) * TS * KWS;
            const u32* vg2 = vgl + (size_t)(t0 + 1) * TS * VWG;
            #pragma unroll
            for (int rr = 0; rr < 3; rr++) {
                int idx = tid + rr * CTN;
                if (idx < KT4) cp16(sK_u[nxt] + idx * 16, kg2 + idx * 4);
            }
            #pragma unroll
            for (int rr = 0; rr < 4; rr++) {
                int idx = tid + rr * CTN;
                int row = idx >> 2, mm = idx & 3;
                cp16(sV_u[nxt] + (row * VW + mm * 4) * 4, vg2 + idx * 4);
            }
            CP_COMMIT();
        }

        #pragma unroll
        for (int kg = 0; kg < TS / 16; kg++) {
            // ---- K fragments via 2 ldmatrix (non-trans), shared by both M-tiles
            u32 kbA0, kbA1, kbB0, kbB1, kbA2, kbB2;
            {
                u32 a4 = sK_u[cur] + (kg * 16 * KWS + kOff4) * 4;
                asm volatile("ldmatrix.sync.aligned.m8n8.x4.shared.b16 "
                             "{%0,%1,%2,%3}, [%4];"
                    : "=r"(kbA0), "=r"(kbA1), "=r"(kbB0), "=r"(kbB1) : "r"(a4));
                u32 a2 = sK_u[cur] + (kg * 16 * KWS + kOff2) * 4;
                asm volatile("ldmatrix.sync.aligned.m8n8.x2.shared.b16 "
                             "{%0,%1}, [%2];"
                    : "=r"(kbA2), "=r"(kbB2) : "r"(a2));
            }

            // ---- V fragments: ldmatrix x4 (dims 0..31) + x2 (ones col 32..39)
            u32 vb0[4], vb1[4], vb40, vb41;
            {
                int rrow = lane & 7, mm = lane >> 3;
                u32 a1 = sV_u[cur] + ((kg * 16 + rrow) * VW + mm * 4) * 4;
                u32 a2v = a1 + 8 * VW * 4;
                asm volatile("ldmatrix.sync.aligned.m8n8.x4.trans.shared.b16 "
                             "{%0,%1,%2,%3}, [%4];"
                    : "=r"(vb0[0]), "=r"(vb0[1]), "=r"(vb0[2]), "=r"(vb0[3]) : "r"(a1));
                asm volatile("ldmatrix.sync.aligned.m8n8.x4.trans.shared.b16 "
                             "{%0,%1,%2,%3}, [%4];"
                    : "=r"(vb1[0]), "=r"(vb1[1]), "=r"(vb1[2]), "=r"(vb1[3]) : "r"(a2v));
                u32 a3 = sV_u[cur] +
                    ((kg * 16 + (lane & 7) + ((lane >> 3) & 1) * 8) * VW + 16) * 4;
                asm volatile("ldmatrix.sync.aligned.m8n8.x2.trans.shared.b16 "
                             "{%0,%1}, [%2];"
                    : "=r"(vb40), "=r"(vb41) : "r"(a3));
            }

            // ---- two independent M-tiles share all fragments ----
            #pragma unroll
            for (int t = 0; t < 2; t++) {
                // QK^T: k16 MMA (feats 0..15) + k8 MMA (feats 16..19+bias+pad)
                float sA0 = 0.f, sA1 = 0.f, sA2 = 0.f, sA3 = 0.f;
                float sB0 = 0.f, sB1 = 0.f, sB2 = 0.f, sB3 = 0.f;
                mma_f16(sA0, sA1, sA2, sA3,
                        aq0[t][0], aq0[t][1], aq0[t][2], aq0[t][3],
                        kbA0, kbA1, sA0, sA1, sA2, sA3);
                mma_f16_k8(sA0, sA1, sA2, sA3,
                           aq1[t][0], aq1[t][1], kbA2, sA0, sA1, sA2, sA3);
                mma_f16(sB0, sB1, sB2, sB3,
                        aq0[t][0], aq0[t][1], aq0[t][2], aq0[t][3],
                        kbB0, kbB1, sB0, sB1, sB2, sB3);
                mma_f16_k8(sB0, sB1, sB2, sB3,
                           aq1[t][0], aq1[t][1], kbB2, sB0, sB1, sB2, sB3);

                // pack score pairs -> f16x2, dual-exp via one MUFU op each.
                u32 pa0 = ex2h2(pack_f16(sA0, sA1));   // row g,   keys 2i,2i+1
                u32 pa1 = ex2h2(pack_f16(sA2, sA3));   // row g+8
                u32 pa2 = ex2h2(pack_f16(sB0, sB1));   // row g,   keys 8+2i..
                u32 pa3 = ex2h2(pack_f16(sB2, sB3));   // row g+8

                #pragma unroll
                for (int nt = 0; nt < 4; nt++) {
                    mma_f16(o[t][nt][0], o[t][nt][1], o[t][nt][2], o[t][nt][3],
                            pa0, pa1, pa2, pa3, vb0[nt], vb1[nt],
                            o[t][nt][0], o[t][nt][1], o[t][nt][2], o[t][nt][3]);
                }
                // ones-column: accumulates softmax denominator per row
                mma_f16(o[t][4][0], o[t][4][1], o[t][4][2], o[t][4][3],
                        pa0, pa1, pa2, pa3, vb40, vb41,
                        o[t][4][0], o[t][4][1], o[t][4][2], o[t][4][3]);
            }
        }
    }

    // ---- epilogue: broadcast l (ones-col, i==0 lanes), normalize, residual,
    //      LayerNorm, store ----
    #pragma unroll
    for (int t = 0; t < 2; t++) {
        // l lives at col 32 -> local col 0 -> lanes with i==0
        float l0 = __shfl_sync(0xFFFFFFFFu, o[t][4][0], lane & 28);  // row g
        float l1 = __shfl_sync(0xFFFFFFFFu, o[t][4][2], lane & 28);  // row g+8
        float inv0 = 1.f / l0;
        float inv1 = 1.f / l1;

        #pragma unroll
        for (int half = 0; half < 2; half++) {
            int   row  = qbase + t * 16 + g + half * 8;
            float invl = half == 0 ? inv0 : inv1;
            int   r0   = half == 0 ? 0 : 2;

            const float2* qr = (const float2*)(ques + ((size_t)b * LQ + row) * DIN);
            float x[4][2];
            float ssum = 0.f;
            #pragma unroll
            for (int nt = 0; nt < 4; nt++) {
                float2 qv = qr[nt * 4 + i];
                x[nt][0] = o[t][nt][r0]     * invl + qv.x;
                x[nt][1] = o[t][nt][r0 + 1] * invl + qv.y;
                ssum += x[nt][0] + x[nt][1];
            }
            ssum += __shfl_xor_sync(0xFFFFFFFFu, ssum, 1);
            ssum += __shfl_xor_sync(0xFFFFFFFFu, ssum, 2);
            float m = ssum * (1.f / DIN);
            float v = 0.f;
            #pragma unroll
            for (int nt = 0; nt < 4; nt++) {
                float d0 = x[nt][0] - m, d1 = x[nt][1] - m;
                v += d0 * d0 + d1 * d1;
            }
            v += __shfl_xor_sync(0xFFFFFFFFu, v, 1);
            v += __shfl_xor_sync(0xFFFFFFFFu, v, 2);
            float rs = rsqrtf(v * (1.f / DIN) + EPS);

            float2* po = (float2*)(out + ((size_t)b * LQ + row) * DIN);
            #pragma unroll
            for (int nt = 0; nt < 4; nt++) {
                int col = nt * 8 + 2 * i;
                float2 tt;
                tt.x = (x[nt][0] - m) * rs * __ldg(go + col)     + __ldg(bo + col);
                tt.y = (x[nt][1] - m) * rs * __ldg(go + col + 1) + __ldg(bo + col + 1);
                po[nt * 4 + i] = tt;
            }
        }
    }
}

// ---------------------------------------------------------------------------
extern "C" void kernel_launch(void* const* d_in, const int* in_sizes, int n_in,
                              void* d_out, int out_size)
{
    const float* vals = (const float*)d_in[0];
    const float* keys = (const float*)d_in[1];
    const float* ques = (const float*)d_in[2];
    const void*  mask = d_in[3];
    const float* Wv   = (const float*)d_in[4];
    const float* Wk   = (const float*)d_in[5];
    const float* Wq   = (const float*)d_in[6];
    const float* gk   = (const float*)d_in[7];
    const float* bk   = (const float*)d_in[8];
    const float* gq   = (const float*)d_in[9];
    const float* bq   = (const float*)d_in[10];
    const float* go   = (const float*)d_in[11];
    const float* bo   = (const float*)d_in[12];
    float* out = (float*)d_out;

    dim3 pgrid((NB * LK) / 256, 3);
    proj_kernel<<<pgrid, 256>>>(vals, keys, ques, mask, Wv, Wk, Wq, gk, bk, gq, bq);

    dim3 grid(LQ / 64, NB);
    attn_kernel<<<grid, CTN>>>(ques, go, bo, out);
}

// round 17
// speedup vs baseline: 1.0617x; 1.0617x over previous
#include <cuda_runtime.h>
#include <cstdint>

// Problem constants
#define NB   32
#define LQ   2048
#define LK   2048
#define DIN  32
#define DKQ  20
#define EPS  1e-5f
// fold 1/sqrt(20) * log2(e) into q so scores are in log2 domain
#define QSCALE 0.32258572299984063f   // log2(e)/sqrt(20)
#define BIAS_MASKED (-60000.0f)       // f16-finite; ex2 -> exactly 0

// f16 storage strides (in u32 words = f16 pairs)
#define KWS 12  // K row (global AND smem): feats 0..19 (w0-9), bias@w10, zero w11 -> 48B
#define VWG 16  // V row global: dims 0..31 compact -> 64B
#define VW  20  // V row smem: 16 data words + ones@w16 + zero w17-19 -> 80B
#define QW  16  // Q row: feats 0..19, 1.0@20, zero-pad to 32 f16 -> 64B

typedef unsigned int u32;

// Scratch (allocation-free rule: __device__ globals), f16 pairs as u32
__device__ u32 d_kb[(size_t)NB * LK * KWS];
__device__ u32 d_vb[(size_t)NB * LK * VWG];
__device__ u32 d_qb[(size_t)NB * LQ * QW];

// pack two f32 -> f16x2 (lo = first arg)
__device__ __forceinline__ u32 pack_f16(float lo, float hi) {
    u32 d; asm("cvt.rn.f16x2.f32 %0, %1, %2;" : "=r"(d) : "f"(hi), "f"(lo));
    return d;
}
// dual exp2 on packed f16x2
__device__ __forceinline__ u32 ex2h2(u32 a) {
    u32 d; asm("ex2.approx.f16x2 %0, %1;" : "=r"(d) : "r"(a));
    return d;
}
// m16n8k16 f16 mma: D = A*B + C (fp32 accum)
__device__ __forceinline__ void mma_f16(
    float& d0, float& d1, float& d2, float& d3,
    u32 a0, u32 a1, u32 a2, u32 a3, u32 b0, u32 b1,
    float c0, float c1, float c2, float c3)
{
    asm("mma.sync.aligned.m16n8k16.row.col.f32.f16.f16.f32 "
        "{%0,%1,%2,%3},{%4,%5,%6,%7},{%8,%9},{%10,%11,%12,%13};"
        : "=f"(d0), "=f"(d1), "=f"(d2), "=f"(d3)
        : "r"(a0), "r"(a1), "r"(a2), "r"(a3), "r"(b0), "r"(b1),
          "f"(c0), "f"(c1), "f"(c2), "f"(c3));
}
// m16n8k8 f16 mma (half-depth): covers feats 16..19 + bias + zero pad
__device__ __forceinline__ void mma_f16_k8(
    float& d0, float& d1, float& d2, float& d3,
    u32 a0, u32 a1, u32 b0,
    float c0, float c1, float c2, float c3)
{
    asm("mma.sync.aligned.m16n8k8.row.col.f32.f16.f16.f32 "
        "{%0,%1,%2,%3},{%4,%5},{%6},{%7,%8,%9,%10};"
        : "=f"(d0), "=f"(d1), "=f"(d2), "=f"(d3)
        : "r"(a0), "r"(a1), "r"(b0),
          "f"(c0), "f"(c1), "f"(c2), "f"(c3));
}
__device__ __forceinline__ void cp16(u32 dst, const void* src) {
    asm volatile("cp.async.cg.shared.global [%0], [%1], 16;" :: "r"(dst), "l"(src));
}
#define CP_COMMIT() asm volatile("cp.async.commit_group;")
#define CP_WAIT0()  asm volatile("cp.async.wait_group 0;")

__device__ __forceinline__ float dot4(float4 a, float4 b, float acc) {
    acc = fmaf(a.x, b.x, acc);
    acc = fmaf(a.y, b.y, acc);
    acc = fmaf(a.z, b.z, acc);
    acc = fmaf(a.w, b.w, acc);
    return acc;
}

// ---------------------------------------------------------------------------
// Kernel 1: projections -> f16 (compact layouts), split by blockIdx.y.
// ---------------------------------------------------------------------------
__global__ __launch_bounds__(256) void proj_kernel(
    const float* __restrict__ vals, const float* __restrict__ keys,
    const float* __restrict__ ques, const void* __restrict__ mask_raw,
    const float* __restrict__ Wv, const float* __restrict__ Wk, const float* __restrict__ Wq,
    const float* __restrict__ gk, const float* __restrict__ bk,
    const float* __restrict__ gq, const float* __restrict__ bq)
{
    __shared__ float sW[DIN * DIN];
    __shared__ float sg[DKQ], sb[DKQ];
    __shared__ int s_is_byte;

    int tid  = threadIdx.x;
    int task = blockIdx.y;
    size_t r = (size_t)blockIdx.x * 256 + tid;

    if (task == 0) {
        for (int i = tid; i < DIN * DIN; i += 256) sW[i] = Wv[i];
        __syncthreads();

        float4 xa[8];
        const float4* p4 = (const float4*)(vals + r * DIN);
        #pragma unroll
        for (int i = 0; i < 8; i++) xa[i] = p4[i];

        uint4* o4 = (uint4*)(d_vb + r * VWG);
        #pragma unroll
        for (int half = 0; half < 2; half++) {
            float outr[16];
            #pragma unroll
            for (int o = 0; o < 16; o++) {
                const float4* wr = (const float4*)(sW + (half * 16 + o) * DIN);
                float acc = 0.f;
                #pragma unroll
                for (int d = 0; d < 8; d++) acc = dot4(xa[d], wr[d], acc);
                outr[o] = acc;
            }
            u32 wv[8];
            #pragma unroll
            for (int p = 0; p < 8; p++) wv[p] = pack_f16(outr[2*p], outr[2*p+1]);
            o4[half * 2]     = make_uint4(wv[0], wv[1], wv[2], wv[3]);
            o4[half * 2 + 1] = make_uint4(wv[4], wv[5], wv[6], wv[7]);
        }
    } else {
        const float* W  = (task == 1) ? Wk : Wq;
        const float* gg = (task == 1) ? gk : gq;
        const float* bb = (task == 1) ? bk : bq;
        const float* in = (task == 1) ? keys : ques;
        for (int i = tid; i < DKQ * DIN; i += 256) sW[i] = W[i];
        if (tid < DKQ) { sg[tid] = gg[tid]; sb[tid] = bb[tid]; }
        if (task == 1 && tid == 0) {
            // Detect mask storage: numpy bool (1 byte) vs int32 coercion.
            const unsigned int* wd = (const unsigned int*)mask_raw;
            unsigned int acc = 0;
            for (int k = 0; k < 64; k++) acc |= wd[k] & 0xFFFFFF00u;
            s_is_byte = (acc != 0u);
        }
        __syncthreads();

        float4 xa[8];
        const float4* p4 = (const float4*)(in + r * DIN);
        #pragma unroll
        for (int i = 0; i < 8; i++) xa[i] = p4[i];

        float y[DKQ];
        #pragma unroll
        for (int o = 0; o < DKQ; o++) {
            const float4* wr = (const float4*)(sW + o * DIN);
            float acc = 0.f;
            #pragma unroll
            for (int d = 0; d < 8; d++) acc = dot4(xa[d], wr[d], acc);
            y[o] = acc;
        }
        float m = 0.f;
        #pragma unroll
        for (int c = 0; c < DKQ; c++) m += y[c];
        m *= (1.f / DKQ);
        float v = 0.f;
        #pragma unroll
        for (int c = 0; c < DKQ; c++) { float d = y[c] - m; v += d * d; }
        v *= (1.f / DKQ);
        float rs = rsqrtf(v + EPS);

        if (task == 1) {
            #pragma unroll
            for (int c = 0; c < DKQ; c++) y[c] = (y[c] - m) * rs * sg[c] + sb[c];
            int mv = s_is_byte ? (int)((const unsigned char*)mask_raw)[r]
                               : ((const int*)mask_raw)[r];
            float bias = mv ? BIAS_MASKED : 0.f;   // True masks OUT
            u32 wv[KWS];
            #pragma unroll
            for (int p = 0; p < 10; p++) wv[p] = pack_f16(y[2*p], y[2*p+1]);
            wv[10] = pack_f16(bias, 0.f);
            wv[11] = 0u;
            uint4* o4 = (uint4*)(d_kb + r * KWS);
            #pragma unroll
            for (int i = 0; i < 3; i++)
                o4[i] = make_uint4(wv[4*i], wv[4*i+1], wv[4*i+2], wv[4*i+3]);
        } else {
            #pragma unroll
            for (int c = 0; c < DKQ; c++)
                y[c] = ((y[c] - m) * rs * sg[c] + sb[c]) * QSCALE;
            u32 wv[QW];
            #pragma unroll
            for (int p = 0; p < 10; p++) wv[p] = pack_f16(y[2*p], y[2*p+1]);
            wv[10] = pack_f16(1.0f, 0.f);
            #pragma unroll
            for (int p = 11; p < QW; p++) wv[p] = 0u;
            uint4* o4 = (uint4*)(d_qb + r * QW);
            #pragma unroll
            for (int i = 0; i < 4; i++)
                o4[i] = make_uint4(wv[4*i], wv[4*i+1], wv[4*i+2], wv[4*i+3]);
        }
    }
}

// ---------------------------------------------------------------------------
// Kernel 2: flash attention with INTRA-CTA key split.
// CTA = 128 thr = 4 warps, 64 queries, grid=(LQ/64,NB)=1024 CTAs.
// Warps 0,1: chunks 0-1 of each tile for queries 0-31 / 32-63 (2 m16 tiles,
// shared fragments). Warps 2,3: chunks 2-3 for the same queries.
// Partial (o, l) accumulators combined additively via smem at the end
// (no-max softmax => plain addition). QK = k16+k8 MMA, ldmatrix frags,
// cp.async double-buffered TS=64 tiles.
// ---------------------------------------------------------------------------
#define TS 64
#define NT (LK / TS)
#define KT4 (TS * KWS / 4)   // 192 uint4 per K tile
#define VT4 (TS * VWG / 4)   // 256 uint4 per V tile

__global__ __launch_bounds__(128) void attn_kernel(
    const float* __restrict__ ques,
    const float* __restrict__ go, const float* __restrict__ bo,
    float* __restrict__ out)
{
    __shared__ u32 sK[2][TS * KWS];   // 2 x 3072 B
    __shared__ u32 sV[2][TS * VW];    // 2 x 5120 B
    __shared__ float sX[2][32][40];   // partial exchange (warps 2,3 -> 0,1)

    int tid  = threadIdx.x;
    int w    = tid >> 5;
    int lane = tid & 31;
    int g    = lane >> 2;   // group id (0..7)
    int i    = lane & 3;    // thread in group (0..3)
    int b    = blockIdx.y;
    int qhalf = w & 1;                       // which 32-query group
    int khalf = w >> 1;                      // which key half (chunks)
    int qbase = blockIdx.x * 64 + qhalf * 32;

    // ---- Q fragments: two m16 tiles x (k16 chunk + k8 chunk) ----
    u32 aq0[2][4], aq1[2][2];
    #pragma unroll
    for (int t = 0; t < 2; t++) {
        const u32* q0p = d_qb + ((size_t)b * LQ + qbase + t * 16 + g) * QW;
        const u32* q1p = q0p + 8 * QW;
        aq0[t][0] = q0p[i];
        aq0[t][1] = q1p[i];
        aq0[t][2] = q0p[i + 4];
        aq0[t][3] = q1p[i + 4];
        aq1[t][0] = q0p[8 + i];
        aq1[t][1] = q1p[8 + i];
    }

    // o[t][nt] nt=0..3: output dims; nt=4: ones-column (denominator)
    float o[2][5][4];
    #pragma unroll
    for (int t = 0; t < 2; t++)
        #pragma unroll
        for (int nt = 0; nt < 5; nt++)
            #pragma unroll
            for (int r = 0; r < 4; r++) o[t][nt][r] = 0.f;

    const u32* kgl = d_kb + (size_t)b * LK * KWS;
    const u32* vgl = d_vb + (size_t)b * LK * VWG;

    u32 sK_u[2], sV_u[2];
    sK_u[0] = (u32)__cvta_generic_to_shared(&sK[0][0]);
    sK_u[1] = (u32)__cvta_generic_to_shared(&sK[1][0]);
    sV_u[0] = (u32)__cvta_generic_to_shared(&sV[0][0]);
    sV_u[1] = (u32)__cvta_generic_to_shared(&sV[1][0]);

    // ---- one-time: ones-column + pad words (w16..w19) for BOTH V buffers ----
    {
        int buf = tid >> 6, row = tid & 63;   // 128 threads = 2 bufs x 64 rows
        uint4* p = (uint4*)(&sV[buf][row * VW + 16]);
        *p = make_uint4(pack_f16(1.0f, 0.f), 0u, 0u, 0u);
    }

    // ---- preamble: async load tile 0 ----
    {
        #pragma unroll
        for (int rr = 0; rr < 2; rr++) {
            int idx = tid + rr * 128;
            if (idx < KT4) cp16(sK_u[0] + idx * 16, kgl + idx * 4);
        }
        #pragma unroll
        for (int rr = 0; rr < 2; rr++) {
            int idx = tid + rr * 128;
            int row = idx >> 2, mm = idx & 3;
            cp16(sV_u[0] + (row * VW + mm * 4) * 4, vgl + idx * 4);
        }
        CP_COMMIT();
    }

    // per-lane constant parts of the ldmatrix-K addresses
    int kmM  = lane >> 3;          // matrix id 0..3 (x4)
    int kmR  = lane & 7;           // row within matrix
    int kOff4 = ((kmM >> 1) * 8 + kmR) * KWS + (kmM & 1) * 4;  // words
    int kOff2 = (((lane >> 3) & 1) * 8 + kmR) * KWS + 8;       // words

    for (int t0 = 0; t0 < NT; t0++) {
        int cur = t0 & 1;
        CP_WAIT0();
        __syncthreads();   // tile t0 ready; all warps done with buffer we refill

        // prefetch tile t0+1 (overlaps with compute below)
        if (t0 + 1 < NT) {
            int nxt = cur ^ 1;
            const u32* kg2 = kgl + (size_t)(t0 + 1) * TS * KWS;
            const u32* vg2 = vgl + (size_t)(t0 + 1) * TS * VWG;
            #pragma unroll
            for (int rr = 0; rr < 2; rr++) {
                int idx = tid + rr * 128;
                if (idx < KT4) cp16(sK_u[nxt] + idx * 16, kg2 + idx * 4);
            }
            #pragma unroll
            for (int rr = 0; rr < 2; rr++) {
                int idx = tid + rr * 128;
                int row = idx >> 2, mm = idx & 3;
                cp16(sV_u[nxt] + (row * VW + mm * 4) * 4, vg2 + idx * 4);
            }
            CP_COMMIT();
        }

        #pragma unroll
        for (int kk = 0; kk < 2; kk++) {
            int kg = khalf * 2 + kk;   // warps 0,1: chunks 0,1; warps 2,3: 2,3
            // ---- K fragments via 2 ldmatrix (non-trans), shared by both M-tiles
            u32 kbA0, kbA1, kbB0, kbB1, kbA2, kbB2;
            {
                u32 a4 = sK_u[cur] + (kg * 16 * KWS + kOff4) * 4;
                asm volatile("ldmatrix.sync.aligned.m8n8.x4.shared.b16 "
                             "{%0,%1,%2,%3}, [%4];"
                    : "=r"(kbA0), "=r"(kbA1), "=r"(kbB0), "=r"(kbB1) : "r"(a4));
                u32 a2 = sK_u[cur] + (kg * 16 * KWS + kOff2) * 4;
                asm volatile("ldmatrix.sync.aligned.m8n8.x2.shared.b16 "
                             "{%0,%1}, [%2];"
                    : "=r"(kbA2), "=r"(kbB2) : "r"(a2));
            }

            // ---- V fragments: ldmatrix x4 (dims 0..31) + x2 (ones col 32..39)
            u32 vb0[4], vb1[4], vb40, vb41;
            {
                int rrow = lane & 7, mm = lane >> 3;
                u32 a1 = sV_u[cur] + ((kg * 16 + rrow) * VW + mm * 4) * 4;
                u32 a2v = a1 + 8 * VW * 4;
                asm volatile("ldmatrix.sync.aligned.m8n8.x4.trans.shared.b16 "
                             "{%0,%1,%2,%3}, [%4];"
                    : "=r"(vb0[0]), "=r"(vb0[1]), "=r"(vb0[2]), "=r"(vb0[3]) : "r"(a1));
                asm volatile("ldmatrix.sync.aligned.m8n8.x4.trans.shared.b16 "
                             "{%0,%1,%2,%3}, [%4];"
                    : "=r"(vb1[0]), "=r"(vb1[1]), "=r"(vb1[2]), "=r"(vb1[3]) : "r"(a2v));
                u32 a3 = sV_u[cur] +
                    ((kg * 16 + (lane & 7) + ((lane >> 3) & 1) * 8) * VW + 16) * 4;
                asm volatile("ldmatrix.sync.aligned.m8n8.x2.trans.shared.b16 "
                             "{%0,%1}, [%2];"
                    : "=r"(vb40), "=r"(vb41) : "r"(a3));
            }

            // ---- two independent M-tiles share all fragments ----
            #pragma unroll
            for (int t = 0; t < 2; t++) {
                // QK^T: k16 MMA (feats 0..15) + k8 MMA (feats 16..19+bias+pad)
                float sA0 = 0.f, sA1 = 0.f, sA2 = 0.f, sA3 = 0.f;
                float sB0 = 0.f, sB1 = 0.f, sB2 = 0.f, sB3 = 0.f;
                mma_f16(sA0, sA1, sA2, sA3,
                        aq0[t][0], aq0[t][1], aq0[t][2], aq0[t][3],
                        kbA0, kbA1, sA0, sA1, sA2, sA3);
                mma_f16_k8(sA0, sA1, sA2, sA3,
                           aq1[t][0], aq1[t][1], kbA2, sA0, sA1, sA2, sA3);
                mma_f16(sB0, sB1, sB2, sB3,
                        aq0[t][0], aq0[t][1], aq0[t][2], aq0[t][3],
                        kbB0, kbB1, sB0, sB1, sB2, sB3);
                mma_f16_k8(sB0, sB1, sB2, sB3,
                           aq1[t][0], aq1[t][1], kbB2, sB0, sB1, sB2, sB3);

                // pack score pairs -> f16x2, dual-exp via one MUFU op each.
                u32 pa0 = ex2h2(pack_f16(sA0, sA1));   // row g,   keys 2i,2i+1
                u32 pa1 = ex2h2(pack_f16(sA2, sA3));   // row g+8
                u32 pa2 = ex2h2(pack_f16(sB0, sB1));   // row g,   keys 8+2i..
                u32 pa3 = ex2h2(pack_f16(sB2, sB3));   // row g+8

                #pragma unroll
                for (int nt = 0; nt < 4; nt++) {
                    mma_f16(o[t][nt][0], o[t][nt][1], o[t][nt][2], o[t][nt][3],
                            pa0, pa1, pa2, pa3, vb0[nt], vb1[nt],
                            o[t][nt][0], o[t][nt][1], o[t][nt][2], o[t][nt][3]);
                }
                // ones-column: accumulates softmax denominator per row
                mma_f16(o[t][4][0], o[t][4][1], o[t][4][2], o[t][4][3],
                        pa0, pa1, pa2, pa3, vb40, vb41,
                        o[t][4][0], o[t][4][1], o[t][4][2], o[t][4][3]);
            }
        }
    }

    // ---- combine key-half partials: warps 2,3 -> warps 0,1 (additive) ----
    __syncthreads();
    if (w >= 2) {
        float* p = &sX[w - 2][lane][0];
        int idx = 0;
        #pragma unroll
        for (int t = 0; t < 2; t++)
            #pragma unroll
            for (int nt = 0; nt < 5; nt++)
                #pragma unroll
                for (int r = 0; r < 4; r++) p[idx++] = o[t][nt][r];
    }
    __syncthreads();
    if (w < 2) {
        const float* p = &sX[w][lane][0];
        int idx = 0;
        #pragma unroll
        for (int t = 0; t < 2; t++)
            #pragma unroll
            for (int nt = 0; nt < 5; nt++)
                #pragma unroll
                for (int r = 0; r < 4; r++) o[t][nt][r] += p[idx++];

        // ---- epilogue (warps 0,1 only): broadcast l, normalize, residual,
        //      LayerNorm, store ----
        #pragma unroll
        for (int t = 0; t < 2; t++) {
            // l lives at col 32 -> local col 0 -> lanes with i==0
            float l0 = __shfl_sync(0xFFFFFFFFu, o[t][4][0], lane & 28);  // row g
            float l1 = __shfl_sync(0xFFFFFFFFu, o[t][4][2], lane & 28);  // row g+8
            float inv0 = 1.f / l0;
            float inv1 = 1.f / l1;

            #pragma unroll
            for (int half = 0; half < 2; half++) {
                int   row  = qbase + t * 16 + g + half * 8;
                float invl = half == 0 ? inv0 : inv1;
                int   r0   = half == 0 ? 0 : 2;

                const float2* qr = (const float2*)(ques + ((size_t)b * LQ + row) * DIN);
                float x[4][2];
                float ssum = 0.f;
                #pragma unroll
                for (int nt = 0; nt < 4; nt++) {
                    float2 qv = qr[nt * 4 + i];
                    x[nt][0] = o[t][nt][r0]     * invl + qv.x;
                    x[nt][1] = o[t][nt][r0 + 1] * invl + qv.y;
                    ssum += x[nt][0] + x[nt][1];
                }
                ssum += __shfl_xor_sync(0xFFFFFFFFu, ssum, 1);
                ssum += __shfl_xor_sync(0xFFFFFFFFu, ssum, 2);
                float m = ssum * (1.f / DIN);
                float v = 0.f;
                #pragma unroll
                for (int nt = 0; nt < 4; nt++) {
                    float d0 = x[nt][0] - m, d1 = x[nt][1] - m;
                    v += d0 * d0 + d1 * d1;
                }
                v += __shfl_xor_sync(0xFFFFFFFFu, v, 1);
                v += __shfl_xor_sync(0xFFFFFFFFu, v, 2);
                float rs = rsqrtf(v * (1.f / DIN) + EPS);

                float2* po = (float2*)(out + ((size_t)b * LQ + row) * DIN);
                #pragma unroll
                for (int nt = 0; nt < 4; nt++) {
                    int col = nt * 8 + 2 * i;
                    float2 tt;
                    tt.x = (x[nt][0] - m) * rs * __ldg(go + col)     + __ldg(bo + col);
                    tt.y = (x[nt][1] - m) * rs * __ldg(go + col + 1) + __ldg(bo + col + 1);
                    po[nt * 4 + i] = tt;
                }
            }
        }
    }
}

// ---------------------------------------------------------------------------
extern "C" void kernel_launch(void* const* d_in, const int* in_sizes, int n_in,
                              void* d_out, int out_size)
{
    const float* vals = (const float*)d_in[0];
    const float* keys = (const float*)d_in[1];
    const float* ques = (const float*)d_in[2];
    const void*  mask = d_in[3];
    const float* Wv   = (const float*)d_in[4];
    const float* Wk   = (const float*)d_in[5];
    const float* Wq   = (const float*)d_in[6];
    const float* gk   = (const float*)d_in[7];
    const float* bk   = (const float*)d_in[8];
    const float* gq   = (const float*)d_in[9];
    const float* bq   = (const float*)d_in[10];
    const float* go   = (const float*)d_in[11];
    const float* bo   = (const float*)d_in[12];
    float* out = (float*)d_out;

    dim3 pgrid((NB * LK) / 256, 3);
    proj_kernel<<<pgrid, 256>>>(vals, keys, ques, mask, Wv, Wk, Wq, gk, bk, gq, bq);

    dim3 grid(LQ / 64, NB);
    attn_kernel<<<grid, 128>>>(ques, go, bo, out);
}